// round 11
// baseline (speedup 1.0000x reference)
#include <cuda_runtime.h>
#include <cstdint>

// Problem constants: B=128, T=2048, D=256, LAMDA=0.5
#define B_ 128
#define T_ 2048
#define D_ 256
#define S_ 32                          // T-splits (chunks) per (b, tensor)
#define ROWS_ITEM (T_ / S_)            // 64 rows per chunk
#define NW 8
#define NTHREADS 256
#define GRID_MAIN 592                  // 148 SMs x 4 CTAs
#define CPT (GRID_MAIN / 2)            // 296 CTAs per tensor type
#define NIT (B_ * S_)                  // 4096 chunks per tensor
#define NDOTS (B_ * D_)                // 32768 mids row-dots
#define ROWS_W (ROWS_ITEM / NW)        // 8 rows per warp per chunk
#define NSTG 4                         // per-warp smem pipeline stages (1 row each)

// Globals (zero-initialized; counters monotonic + modular -> graph-replay safe).
__device__ float g_mids[B_ * D_];
__device__ float g_pa[NIT][258];   // aspect partials (acc[256], L at [256])
__device__ float g_p1[NIT][258];   // sentiment-sentiment partials
__device__ float g_p2[NIT][258];   // sentiment-aspect partials
__device__ unsigned g_bar;         // aspect-side barrier counter (+CPT per launch)
__device__ unsigned g_cnt_s[B_];   // sentiment completion counters (+32/launch)
__device__ unsigned g_cnt_a[B_];   // aspect completion counters    (+32/launch)

__device__ __forceinline__ float warp_sum(float v) {
#pragma unroll
    for (int o = 16; o > 0; o >>= 1) v += __shfl_xor_sync(0xffffffffu, v, o);
    return v;
}
__device__ __forceinline__ uint32_t smem_u32(const void* p) {
    uint32_t a;
    asm("{ .reg .u64 t; cvta.to.shared.u64 t, %1; cvt.u32.u64 %0, t; }"
        : "=r"(a) : "l"(p));
    return a;
}
__device__ __forceinline__ void cp16(uint32_t dst, const void* src) {
    asm volatile("cp.async.cg.shared.global [%0], [%1], 16;"
                 :: "r"(dst), "l"(src) : "memory");
}
__device__ __forceinline__ void cp_commit() {
    asm volatile("cp.async.commit_group;" ::: "memory");
}
__device__ __forceinline__ void cp_wait2() {
    asm volatile("cp.async.wait_group 2;" ::: "memory");
}
// Copy one 1KB row into a per-warp stage; lane l moves bytes [l*16) and [512+l*16).
// Each lane later reads back exactly the bytes it copied -> per-lane
// wait_group visibility is sufficient (no __syncwarp needed).
__device__ __forceinline__ void cp_row(uint32_t dst, const float* src, int lane) {
    cp16(dst + lane * 16, (const char*)src + lane * 16);
    cp16(dst + 512 + lane * 16, (const char*)src + 512 + lane * 16);
    cp_commit();
}
__device__ __forceinline__ float dot8(float4 a, float4 b, float4 c, float4 d) {
    return a.x*b.x + a.y*b.y + a.z*b.z + a.w*b.w
         + c.x*d.x + c.y*d.y + c.z*d.z + c.w*d.w;
}
#define FMA4(acc, s, r) \
    acc.x += (s)*(r).x; acc.y += (s)*(r).y; acc.z += (s)*(r).z; acc.w += (s)*(r).w;

// ---------------------------------------------------------------------------
// k_main: ONE kernel, grid = 592 (4 CTAs/SM). Per-warp cp.async pipelines:
// each warp owns a private 4-stage x 1KB smem ring, prefetching 3 rows ahead
// with cp.async.cg (L1-bypass). Exactly one commit_group per iteration makes
// wait_group(2) loop-invariant; the issue-ahead target rolls into the next
// chunk before the flush so the pipeline never drains. No cross-warp sync in
// the stream loop.
// Even CTAs: prologue -> mids GEMV (overlapped with prefetch) -> barrier ->
//            stream aspect_memory (tanh softmax).
// Odd CTAs:  stream sentiment_memory immediately (two softmax streams).
// 32nd completer of each b performs that b's final combine inline.
// No online max needed: aspect scores = tanh in [-1,1]; sentiment scores are
// O(1) -> plain exp() is safe and equals the reference's shifted softmax.
// Query-side additive terms are constant over t and cancel in the softmax.
// ---------------------------------------------------------------------------
__global__ void __launch_bounds__(NTHREADS, 4) k_main(
    const float* __restrict__ aspect,            // [B,D]
    const float* __restrict__ sentiment_memory,  // [B,T,D]
    const float* __restrict__ aspect_memory,     // [B,T,D]
    const float* __restrict__ mask,              // [B,T]
    const float* __restrict__ W_mul,             // [D,D]
    const float* __restrict__ b_mul,             // [1]
    const float* __restrict__ w_ss,              // [2D] (only [:D] matters)
    const float* __restrict__ w_sa,              // [2D]
    float* __restrict__ out)                     // [2*B*D]
{
    __shared__ __align__(16) float s_pipe[NW][NSTG * D_];   // 32 KB
    __shared__ __align__(16) float s_red[NW * D_];          // 8 KB
    __shared__ float s_lred[NW];
    __shared__ int s_doc;

    const int cta   = blockIdx.x;
    const int ctype = cta & 1;          // 0 = aspect, 1 = sentiment
    const int tcta  = cta >> 1;
    const int tid   = threadIdx.x;
    const int w     = tid >> 5, lane = tid & 31;

    const int nit = (NIT - tcta + CPT - 1) / CPT;
    const float* membase = ctype ? sentiment_memory : aspect_memory;
    const uint32_t pbuf = smem_u32(&s_pipe[w][0]);

    // Warp's row base for chunk j: membase + (b*T + s*64 + w*8)*D
    const int e0 = tcta;
    const float* rb_cur = membase
        + ((size_t)(e0 >> 5) * T_ + (size_t)(e0 & 31) * ROWS_ITEM + w * ROWS_W) * D_;

    // Prologue: 3 rows in flight (before mids GEMV on the aspect side, so the
    // prefetch overlaps it).
#pragma unroll
    for (int r = 0; r < 3; r++)
        cp_row(pbuf + (r & 3) * (D_ * 4), rb_cur + (size_t)r * D_, lane);

    if (ctype == 0) {
        // ---- mids GEMV by aspect CTAs only ----
        const int gid = tcta * NW + w;
        for (int idx = gid; idx < NDOTS; idx += CPT * NW) {
            const int b   = idx >> 8;
            const int row = idx & (D_ - 1);
            const float4* Wr = (const float4*)(W_mul + (size_t)row * D_);
            const float4* Ar = (const float4*)(aspect + (size_t)b * D_);
            float p = dot8(Wr[lane], Ar[lane], Wr[32 + lane], Ar[32 + lane]);
            p = warp_sum(p);
            if (lane == 0) g_mids[b * D_ + row] = p;
        }
        __syncthreads();
        // Replay-safe barrier among the CPT aspect CTAs (monotonic counter).
        if (tid == 0) {
            __threadfence();
            const unsigned old = atomicAdd(&g_bar, 1u);
            const unsigned tgt = (old / CPT + 1u) * CPT;
            while (*(volatile unsigned*)&g_bar < tgt) { }
            __threadfence();
        }
        __syncthreads();
    }

    if (ctype == 1) {
        // ------------- sentiment: two softmax streams -------------
        const float4 w10 = *(const float4*)(w_ss + lane * 4);
        const float4 w11 = *(const float4*)(w_ss + 128 + lane * 4);
        const float4 w20 = *(const float4*)(w_sa + lane * 4);
        const float4 w21 = *(const float4*)(w_sa + 128 + lane * 4);

        for (int j = 0; j < nit; j++) {
            const int e = tcta + CPT * j;
            const int b = e >> 5, s = e & 31;
            const float* mrow = mask + (size_t)b * T_ + s * ROWS_ITEM + w * ROWS_W;

            const float* rb_next = rb_cur;
            if (j + 1 < nit) {
                const int e2 = tcta + CPT * (j + 1);
                rb_next = sentiment_memory
                    + ((size_t)(e2 >> 5) * T_ + (size_t)(e2 & 31) * ROWS_ITEM
                       + w * ROWS_W) * D_;
            }

            float l1 = 0.f, l2 = 0.f;
            float4 p0 = {0,0,0,0}, p1 = {0,0,0,0};
            float4 q0 = {0,0,0,0}, q1 = {0,0,0,0};

#pragma unroll
            for (int r = 0; r < ROWS_W; r++) {
                cp_wait2();
                const float* stg = &s_pipe[w][(r & 3) * D_];
                const float4 r0 = *(const float4*)&stg[lane * 4];
                const float4 r1 = *(const float4*)&stg[128 + lane * 4];
                const float mk = mrow[r];

                float d1 = dot8(r0, w10, r1, w11);
                float d2 = dot8(r0, w20, r1, w21);
#pragma unroll
                for (int o = 16; o > 0; o >>= 1) {
                    d1 += __shfl_xor_sync(0xffffffffu, d1, o);
                    d2 += __shfl_xor_sync(0xffffffffu, d2, o);
                }
                const float pe1 = __expf(d1) * mk;
                const float pe2 = __expf(d2) * mk;
                l1 += pe1;  l2 += pe2;
                FMA4(p0, pe1, r0)  FMA4(p1, pe1, r1)
                FMA4(q0, pe2, r0)  FMA4(q1, pe2, r1)

                // Issue-ahead: row r+3 of this chunk, or row r-5 of the next.
                const int ra = r + 3;
                if (ra < ROWS_W)
                    cp_row(pbuf + (ra & 3) * (D_ * 4), rb_cur + (size_t)ra * D_, lane);
                else if (j + 1 < nit)
                    cp_row(pbuf + (ra & 3) * (D_ * 4),
                           rb_next + (size_t)(ra - ROWS_W) * D_, lane);
                else
                    cp_commit();   // empty group keeps wait_group(2) invariant
            }
            rb_cur = rb_next;

            // flush stream 1
            *(float4*)&s_red[w * D_ + lane * 4]       = p0;
            *(float4*)&s_red[w * D_ + 128 + lane * 4] = p1;
            if (lane == 0) s_lred[w] = l1;
            __syncthreads();
            {
                float v = 0.f, L = 0.f;
#pragma unroll
                for (int ww = 0; ww < NW; ww++) { v += s_red[ww * D_ + tid]; L += s_lred[ww]; }
                g_p1[e][tid] = v;
                if (tid == 0) g_p1[e][256] = L;
            }
            __syncthreads();
            // flush stream 2
            *(float4*)&s_red[w * D_ + lane * 4]       = q0;
            *(float4*)&s_red[w * D_ + 128 + lane * 4] = q1;
            if (lane == 0) s_lred[w] = l2;
            __syncthreads();
            {
                float v = 0.f, L = 0.f;
#pragma unroll
                for (int ww = 0; ww < NW; ww++) { v += s_red[ww * D_ + tid]; L += s_lred[ww]; }
                g_p2[e][tid] = v;
                if (tid == 0) g_p2[e][256] = L;
            }
            __syncthreads();

            // Fused combine: 32nd completer of b merges all its partials.
            if (tid == 0) {
                __threadfence();
                const unsigned old = atomicAdd(&g_cnt_s[b], 1u);
                s_doc = ((old & 31u) == 31u);
            }
            __syncthreads();
            if (s_doc) {
                __threadfence();
                float v1 = 0.f, L1 = 0.f, v2 = 0.f, L2 = 0.f;
#pragma unroll 8
                for (int s2 = 0; s2 < S_; s2++) {
                    const int i = b * S_ + s2;
                    v1 += g_p1[i][tid];  L1 += g_p1[i][256];
                    v2 += g_p2[i][tid];  L2 += g_p2[i][256];
                }
                out[b * D_ + tid] = 0.5f * (v1 / L1) + 0.5f * (v2 / L2);
            }
            __syncthreads();
        }
    } else {
        // ------------- aspect: tanh-score softmax -------------
        const float bm = b_mul[0];
        for (int j = 0; j < nit; j++) {
            const int e = tcta + CPT * j;
            const int b = e >> 5;
            const float4 md0 = *(const float4*)(g_mids + b * D_ + lane * 4);
            const float4 md1 = *(const float4*)(g_mids + b * D_ + 128 + lane * 4);

            const float* rb_next = rb_cur;
            if (j + 1 < nit) {
                const int e2 = tcta + CPT * (j + 1);
                rb_next = aspect_memory
                    + ((size_t)(e2 >> 5) * T_ + (size_t)(e2 & 31) * ROWS_ITEM
                       + w * ROWS_W) * D_;
            }

            float l = 0.f;
            float4 a0 = {0,0,0,0}, a1 = {0,0,0,0};

#pragma unroll
            for (int r = 0; r < ROWS_W; r++) {
                cp_wait2();
                const float* stg = &s_pipe[w][(r & 3) * D_];
                const float4 r0 = *(const float4*)&stg[lane * 4];
                const float4 r1 = *(const float4*)&stg[128 + lane * 4];

                float p = dot8(r0, md0, r1, md1);
                p = warp_sum(p);
                const float pe = __expf(tanhf(p + bm));
                l += pe;
                FMA4(a0, pe, r0)  FMA4(a1, pe, r1)

                const int ra = r + 3;
                if (ra < ROWS_W)
                    cp_row(pbuf + (ra & 3) * (D_ * 4), rb_cur + (size_t)ra * D_, lane);
                else if (j + 1 < nit)
                    cp_row(pbuf + (ra & 3) * (D_ * 4),
                           rb_next + (size_t)(ra - ROWS_W) * D_, lane);
                else
                    cp_commit();
            }
            rb_cur = rb_next;

            *(float4*)&s_red[w * D_ + lane * 4]       = a0;
            *(float4*)&s_red[w * D_ + 128 + lane * 4] = a1;
            if (lane == 0) s_lred[w] = l;
            __syncthreads();
            {
                float v = 0.f, L = 0.f;
#pragma unroll
                for (int ww = 0; ww < NW; ww++) { v += s_red[ww * D_ + tid]; L += s_lred[ww]; }
                g_pa[e][tid] = v;
                if (tid == 0) g_pa[e][256] = L;
            }
            __syncthreads();

            if (tid == 0) {
                __threadfence();
                const unsigned old = atomicAdd(&g_cnt_a[b], 1u);
                s_doc = ((old & 31u) == 31u);
            }
            __syncthreads();
            if (s_doc) {
                __threadfence();
                float va = 0.f, La = 0.f;
#pragma unroll 8
                for (int s2 = 0; s2 < S_; s2++) {
                    const int i = b * S_ + s2;
                    va += g_pa[i][tid];  La += g_pa[i][256];
                }
                out[B_ * D_ + b * D_ + tid] = aspect[b * D_ + tid] + va / La;
            }
            __syncthreads();
        }
    }
}

// ---------------------------------------------------------------------------
// kernel_launch. Inputs (metadata order):
//  0 sentiment  1 aspect  2 sentiment_memory  3 aspect_memory  4 mask
//  5 W_mul  6 b_mul  7 w_ss  8 b_ss  9 w_sa  10 b_sa
// Query-side additive terms (w[D:], biases) cancel in the softmax -> unused.
// Output: sentiment_out [0, B*D), aspect_out [B*D, 2*B*D).
// ---------------------------------------------------------------------------
extern "C" void kernel_launch(void* const* d_in, const int* in_sizes, int n_in,
                              void* d_out, int out_size)
{
    const float* aspect           = (const float*)d_in[1];
    const float* sentiment_memory = (const float*)d_in[2];
    const float* aspect_memory    = (const float*)d_in[3];
    const float* mask             = (const float*)d_in[4];
    const float* W_mul            = (const float*)d_in[5];
    const float* b_mul            = (const float*)d_in[6];
    const float* w_ss             = (const float*)d_in[7];
    const float* w_sa             = (const float*)d_in[9];
    float* out = (float*)d_out;

    k_main<<<GRID_MAIN, NTHREADS>>>(
        aspect, sentiment_memory, aspect_memory, mask, W_mul, b_mul,
        w_ss, w_sa, out);
}

// round 14
// speedup vs baseline: 1.3350x; 1.3350x over previous
#include <cuda_runtime.h>
#include <cstdint>

// Problem constants: B=128, T=2048, D=256, LAMDA=0.5
#define B_ 128
#define T_ 2048
#define D_ 256
#define S_ 32                          // 64-row chunks per (b, tensor)
#define ROWS_ITEM 64
#define NW 4                           // warps per CTA (small CTA -> cheap flush)
#define NTHREADS 128
#define GRID_MAIN 1184                 // 148 SMs x 8 CTAs
#define CPT (GRID_MAIN / 2)            // 592 CTAs per tensor type
#define NIT (B_ * S_)                  // 4096 chunks per tensor
#define NDOTS (B_ * D_)                // 32768 mids row-dots
#define ROWS_W (ROWS_ITEM / NW)        // 16 rows per warp per chunk

// Globals (zero-initialized). Counters monotonic+modular -> graph-replay safe.
// Partials are written fresh every launch before being read (proven R10 scheme).
__device__ float g_mids[B_ * D_];
__device__ float g_pa[NIT][258];   // aspect partials (acc[256], L at [256])
__device__ float g_p1[NIT][258];   // sentiment-sentiment partials
__device__ float g_p2[NIT][258];   // sentiment-aspect partials
__device__ unsigned g_bar;         // aspect-side barrier counter (+CPT/launch)
__device__ unsigned g_cnt_s[B_];   // sentiment chunk counters (+32/launch)
__device__ unsigned g_cnt_a[B_];   // aspect chunk counters    (+32/launch)

__device__ __forceinline__ float warp_sum(float v) {
#pragma unroll
    for (int o = 16; o > 0; o >>= 1) v += __shfl_xor_sync(0xffffffffu, v, o);
    return v;
}
__device__ __forceinline__ float dot8(float4 a, float4 b, float4 c, float4 d) {
    return a.x*b.x + a.y*b.y + a.z*b.z + a.w*b.w
         + c.x*d.x + c.y*d.y + c.z*d.z + c.w*d.w;
}
#define FMA4(acc, s, r) \
    acc.x += (s)*(r).x; acc.y += (s)*(r).y; acc.z += (s)*(r).z; acc.w += (s)*(r).w;

// ---------------------------------------------------------------------------
// k_main: ONE kernel, grid = 1184 (8 CTAs/SM, 32 warps/SM). Small 4-warp CTAs
// make the per-chunk flush cheap (4-warp barrier, 4-deep smem reduction), and
// 16 rows/warp halves the flush count vs R10. Proven cross-CTA protocol:
// per-chunk partial arrays written with plain STGs + per-chunk counter; the
// CTA seeing (old&31)==31 for b performs b's final combine.
// Even CTAs: mids GEMV -> barrier (aspect half only) -> stream aspect_memory
//            (tanh-score softmax).
// Odd CTAs:  stream sentiment_memory immediately (two softmax streams, fused
//            single-barrier-pair flush).
// No online max needed: aspect scores = tanh in [-1,1]; sentiment scores are
// O(1) -> plain exp() is safe and equals the reference's shifted softmax.
// Query-side additive terms are constant over t and cancel in the softmax.
// ---------------------------------------------------------------------------
__global__ void __launch_bounds__(NTHREADS, 8) k_main(
    const float* __restrict__ aspect,            // [B,D]
    const float* __restrict__ sentiment_memory,  // [B,T,D]
    const float* __restrict__ aspect_memory,     // [B,T,D]
    const float* __restrict__ mask,              // [B,T]
    const float* __restrict__ W_mul,             // [D,D]
    const float* __restrict__ b_mul,             // [1]
    const float* __restrict__ w_ss,              // [2D] (only [:D] matters)
    const float* __restrict__ w_sa,              // [2D]
    float* __restrict__ out)                     // [2*B*D]
{
    __shared__ __align__(16) float s_red[2 * NW * D_];   // 8 KB (P half, Q half)
    __shared__ float s_lred[2 * NW];
    __shared__ int s_doc;

    const int cta   = blockIdx.x;
    const int ctype = cta & 1;          // 0 = aspect, 1 = sentiment
    const int tcta  = cta >> 1;
    const int tid   = threadIdx.x;
    const int w     = tid >> 5, lane = tid & 31;

    const int nit = (NIT - tcta + CPT - 1) / CPT;   // 6 or 7 chunks

    if (ctype == 0) {
        // ---- mids GEMV by aspect CTAs only (sentiment half streams now) ----
        const int gid = tcta * NW + w;
        for (int idx = gid; idx < NDOTS; idx += CPT * NW) {
            const int b   = idx >> 8;
            const int row = idx & (D_ - 1);
            const float4* Wr = (const float4*)(W_mul + (size_t)row * D_);
            const float4* Ar = (const float4*)(aspect + (size_t)b * D_);
            float p = dot8(Wr[lane], Ar[lane], Wr[32 + lane], Ar[32 + lane]);
            p = warp_sum(p);
            if (lane == 0) g_mids[b * D_ + row] = p;
        }
        __threadfence();   // release own g_mids writes (every thread)
        __syncthreads();
        // Replay-safe barrier among the CPT aspect CTAs (monotonic counter).
        if (tid == 0) {
            const unsigned old = atomicAdd(&g_bar, 1u);
            const unsigned tgt = (old / CPT + 1u) * CPT;
            while (*(volatile unsigned*)&g_bar < tgt) { }
        }
        __syncthreads();
        __threadfence();   // acquire
    }

    if (ctype == 1) {
        // ------------- sentiment: two softmax streams -------------
        const float4 w10 = *(const float4*)(w_ss + lane * 4);
        const float4 w11 = *(const float4*)(w_ss + 128 + lane * 4);
        const float4 w20 = *(const float4*)(w_sa + lane * 4);
        const float4 w21 = *(const float4*)(w_sa + 128 + lane * 4);

        for (int j = 0; j < nit; j++) {
            const int e = tcta + CPT * j;
            const int b = e >> 5, s = e & 31;
            const float4* m4  = (const float4*)(sentiment_memory
                              + ((size_t)b * T_ + (size_t)s * ROWS_ITEM
                                 + w * ROWS_W) * D_);
            const float* mrow = mask + (size_t)b * T_ + (size_t)s * ROWS_ITEM
                              + w * ROWS_W;

            float l1 = 0.f, l2 = 0.f;
            float4 P0 = {0,0,0,0}, P1 = {0,0,0,0};
            float4 Q0 = {0,0,0,0}, Q1 = {0,0,0,0};

#pragma unroll
            for (int rr = 0; rr < ROWS_W; rr += 2) {
                const float4 r0a = __ldcs(&m4[(size_t)rr * 64 + lane]);
                const float4 r1a = __ldcs(&m4[(size_t)rr * 64 + 32 + lane]);
                const float4 r0b = __ldcs(&m4[(size_t)(rr + 1) * 64 + lane]);
                const float4 r1b = __ldcs(&m4[(size_t)(rr + 1) * 64 + 32 + lane]);
                const float mka = mrow[rr];
                const float mkb = mrow[rr + 1];

                float d1a = dot8(r0a, w10, r1a, w11);
                float d2a = dot8(r0a, w20, r1a, w21);
                float d1b = dot8(r0b, w10, r1b, w11);
                float d2b = dot8(r0b, w20, r1b, w21);
#pragma unroll
                for (int o = 16; o > 0; o >>= 1) {
                    d1a += __shfl_xor_sync(0xffffffffu, d1a, o);
                    d2a += __shfl_xor_sync(0xffffffffu, d2a, o);
                    d1b += __shfl_xor_sync(0xffffffffu, d1b, o);
                    d2b += __shfl_xor_sync(0xffffffffu, d2b, o);
                }
                const float pe1a = __expf(d1a) * mka;
                const float pe2a = __expf(d2a) * mka;
                const float pe1b = __expf(d1b) * mkb;
                const float pe2b = __expf(d2b) * mkb;
                l1 += pe1a + pe1b;
                l2 += pe2a + pe2b;
                FMA4(P0, pe1a, r0a)  FMA4(P1, pe1a, r1a)
                FMA4(Q0, pe2a, r0a)  FMA4(Q1, pe2a, r1a)
                FMA4(P0, pe1b, r0b)  FMA4(P1, pe1b, r1b)
                FMA4(Q0, pe2b, r0b)  FMA4(Q1, pe2b, r1b)
            }

            // ---- fused flush: both streams, one barrier pair ----
            *(float4*)&s_red[w * D_ + lane * 4]                 = P0;
            *(float4*)&s_red[w * D_ + 128 + lane * 4]           = P1;
            *(float4*)&s_red[NW * D_ + w * D_ + lane * 4]       = Q0;
            *(float4*)&s_red[NW * D_ + w * D_ + 128 + lane * 4] = Q1;
            if (lane == 0) { s_lred[w] = l1; s_lred[NW + w] = l2; }
            __syncthreads();
            {
                float v1a = 0.f, v1b = 0.f, v2a = 0.f, v2b = 0.f;
#pragma unroll
                for (int ww = 0; ww < NW; ww++) {
                    v1a += s_red[ww * D_ + tid];
                    v1b += s_red[ww * D_ + tid + 128];
                    v2a += s_red[NW * D_ + ww * D_ + tid];
                    v2b += s_red[NW * D_ + ww * D_ + tid + 128];
                }
                const float L1 = s_lred[0] + s_lred[1] + s_lred[2] + s_lred[3];
                const float L2 = s_lred[4] + s_lred[5] + s_lred[6] + s_lred[7];
                g_p1[e][tid] = v1a;  g_p1[e][tid + 128] = v1b;
                g_p2[e][tid] = v2a;  g_p2[e][tid + 128] = v2b;
                if (tid == 0) { g_p1[e][256] = L1; g_p2[e][256] = L2; }
            }
            __threadfence();   // release own partial STGs (every thread)
            __syncthreads();
            if (tid == 0) {
                const unsigned old = atomicAdd(&g_cnt_s[b], 1u);
                s_doc = ((old & 31u) == 31u);
            }
            __syncthreads();
            if (s_doc) {
                __threadfence();   // acquire (per thread)
                float V1a = 0.f, V1b = 0.f, V2a = 0.f, V2b = 0.f;
                float L1 = 0.f, L2 = 0.f;
#pragma unroll 8
                for (int s2 = 0; s2 < S_; s2++) {
                    const int i = b * S_ + s2;
                    V1a += __ldcg(&g_p1[i][tid]);
                    V1b += __ldcg(&g_p1[i][tid + 128]);
                    V2a += __ldcg(&g_p2[i][tid]);
                    V2b += __ldcg(&g_p2[i][tid + 128]);
                    L1  += __ldcg(&g_p1[i][256]);
                    L2  += __ldcg(&g_p2[i][256]);
                }
                out[b * D_ + tid]       = 0.5f * (V1a / L1) + 0.5f * (V2a / L2);
                out[b * D_ + tid + 128] = 0.5f * (V1b / L1) + 0.5f * (V2b / L2);
            }
            __syncthreads();
        }
    } else {
        // ------------- aspect: tanh-score softmax -------------
        const float bm = b_mul[0];
        for (int j = 0; j < nit; j++) {
            const int e = tcta + CPT * j;
            const int b = e >> 5, s = e & 31;
            const float4* m4 = (const float4*)(aspect_memory
                             + ((size_t)b * T_ + (size_t)s * ROWS_ITEM
                                + w * ROWS_W) * D_);
            const float4 md0 = *(const float4*)(g_mids + b * D_ + lane * 4);
            const float4 md1 = *(const float4*)(g_mids + b * D_ + 128 + lane * 4);

            float l = 0.f;
            float4 A0 = {0,0,0,0}, A1 = {0,0,0,0};

#pragma unroll
            for (int rr = 0; rr < ROWS_W; rr += 2) {
                const float4 r0a = __ldcs(&m4[(size_t)rr * 64 + lane]);
                const float4 r1a = __ldcs(&m4[(size_t)rr * 64 + 32 + lane]);
                const float4 r0b = __ldcs(&m4[(size_t)(rr + 1) * 64 + lane]);
                const float4 r1b = __ldcs(&m4[(size_t)(rr + 1) * 64 + 32 + lane]);

                float pa = dot8(r0a, md0, r1a, md1);
                float pb = dot8(r0b, md0, r1b, md1);
#pragma unroll
                for (int o = 16; o > 0; o >>= 1) {
                    pa += __shfl_xor_sync(0xffffffffu, pa, o);
                    pb += __shfl_xor_sync(0xffffffffu, pb, o);
                }
                const float pea = __expf(tanhf(pa + bm));
                const float peb = __expf(tanhf(pb + bm));
                l += pea + peb;
                FMA4(A0, pea, r0a)  FMA4(A1, pea, r1a)
                FMA4(A0, peb, r0b)  FMA4(A1, peb, r1b)
            }

            // ---- flush (single stream) ----
            *(float4*)&s_red[w * D_ + lane * 4]       = A0;
            *(float4*)&s_red[w * D_ + 128 + lane * 4] = A1;
            if (lane == 0) s_lred[w] = l;
            __syncthreads();
            {
                float va = 0.f, vb = 0.f;
#pragma unroll
                for (int ww = 0; ww < NW; ww++) {
                    va += s_red[ww * D_ + tid];
                    vb += s_red[ww * D_ + tid + 128];
                }
                const float L = s_lred[0] + s_lred[1] + s_lred[2] + s_lred[3];
                g_pa[e][tid] = va;  g_pa[e][tid + 128] = vb;
                if (tid == 0) g_pa[e][256] = L;
            }
            __threadfence();   // release (every thread)
            __syncthreads();
            if (tid == 0) {
                const unsigned old = atomicAdd(&g_cnt_a[b], 1u);
                s_doc = ((old & 31u) == 31u);
            }
            __syncthreads();
            if (s_doc) {
                __threadfence();   // acquire (per thread)
                float Va = 0.f, Vb = 0.f, La = 0.f;
#pragma unroll 8
                for (int s2 = 0; s2 < S_; s2++) {
                    const int i = b * S_ + s2;
                    Va += __ldcg(&g_pa[i][tid]);
                    Vb += __ldcg(&g_pa[i][tid + 128]);
                    La += __ldcg(&g_pa[i][256]);
                }
                out[B_ * D_ + b * D_ + tid] = aspect[b * D_ + tid] + Va / La;
                out[B_ * D_ + b * D_ + tid + 128] =
                    aspect[b * D_ + tid + 128] + Vb / La;
            }
            __syncthreads();
        }
    }
}

// ---------------------------------------------------------------------------
// kernel_launch. Inputs (metadata order):
//  0 sentiment  1 aspect  2 sentiment_memory  3 aspect_memory  4 mask
//  5 W_mul  6 b_mul  7 w_ss  8 b_ss  9 w_sa  10 b_sa
// Query-side additive terms (w[D:], biases) cancel in the softmax -> unused.
// Output: sentiment_out [0, B*D), aspect_out [B*D, 2*B*D).
// ---------------------------------------------------------------------------
extern "C" void kernel_launch(void* const* d_in, const int* in_sizes, int n_in,
                              void* d_out, int out_size)
{
    const float* aspect           = (const float*)d_in[1];
    const float* sentiment_memory = (const float*)d_in[2];
    const float* aspect_memory    = (const float*)d_in[3];
    const float* mask             = (const float*)d_in[4];
    const float* W_mul            = (const float*)d_in[5];
    const float* b_mul            = (const float*)d_in[6];
    const float* w_ss             = (const float*)d_in[7];
    const float* w_sa             = (const float*)d_in[9];
    float* out = (float*)d_out;

    k_main<<<GRID_MAIN, NTHREADS>>>(
        aspect, sentiment_memory, aspect_memory, mask, W_mul, b_mul,
        w_ss, w_sa, out);
}

// round 15
// speedup vs baseline: 1.3520x; 1.0128x over previous
#include <cuda_runtime.h>
#include <cstdint>

// Problem constants: B=128, T=2048, D=256, LAMDA=0.5
#define B_ 128
#define T_ 2048
#define D_ 256
#define S_ 32                          // 64-row chunks per (b, tensor)
#define ROWS_ITEM 64
#define NW 4                           // warps per CTA (small CTA -> cheap flush)
#define NTHREADS 128
#define GRID_MAIN 1184                 // 148 SMs x 8 CTAs
#define CPT (GRID_MAIN / 2)            // 592 CTAs per tensor type
#define NIT (B_ * S_)                  // 4096 chunks per tensor
#define NDOTS (B_ * D_)                // 32768 mids row-dots
#define ROWS_W (ROWS_ITEM / NW)        // 16 rows per warp per chunk

// Globals (zero-initialized). Counters monotonic+modular -> graph-replay safe.
// Partials are written fresh every launch before being read (proven scheme).
__device__ float g_mids[B_ * D_];
__device__ float g_pa[NIT][258];   // aspect partials (acc[256], L at [256])
__device__ float g_p1[NIT][258];   // sentiment-sentiment partials
__device__ float g_p2[NIT][258];   // sentiment-aspect partials
__device__ unsigned g_bar;         // aspect-side barrier counter (+CPT/launch)
__device__ unsigned g_cnt_s[B_];   // sentiment chunk counters (+32/launch)
__device__ unsigned g_cnt_a[B_];   // aspect chunk counters    (+32/launch)

__device__ __forceinline__ float warp_sum(float v) {
#pragma unroll
    for (int o = 16; o > 0; o >>= 1) v += __shfl_xor_sync(0xffffffffu, v, o);
    return v;
}
__device__ __forceinline__ float dot8(float4 a, float4 b, float4 c, float4 d) {
    return a.x*b.x + a.y*b.y + a.z*b.z + a.w*b.w
         + c.x*d.x + c.y*d.y + c.z*d.z + c.w*d.w;
}
// Fast tanh: 3 MUFU-class ops instead of libdevice's ~30-instr polynomial.
// |x| form is inf-safe: e^{2|x|} -> inf => RCP -> 0 => result -> +-1 exactly.
// (Scores here reach |x| ~ 100, where (t-1)/(t+1) would be inf/inf = NaN.)
__device__ __forceinline__ float fast_tanh(float x) {
    const float t = __expf(2.0f * fabsf(x));
    const float r = 1.0f - __fdividef(2.0f, t + 1.0f);
    return copysignf(r, x);
}
#define FMA4(acc, s, r) \
    acc.x += (s)*(r).x; acc.y += (s)*(r).y; acc.z += (s)*(r).z; acc.w += (s)*(r).w;

// ---------------------------------------------------------------------------
// k_main: ONE kernel, grid = 1184 (8 CTAs/SM, 32 warps/SM). Small 4-warp CTAs
// make the per-chunk flush cheap; 16 rows/warp keeps flush count low. Proven
// cross-CTA protocol: per-chunk partial arrays (plain STGs) + per-chunk
// counter; the CTA seeing (old&31)==31 for b performs b's final combine.
// Even CTAs: mids GEMV -> barrier (aspect half only) -> stream aspect_memory
//            (fast-tanh-score softmax).
// Odd CTAs:  stream sentiment_memory immediately (two softmax streams, fused
//            single-barrier-pair flush).
// No online max needed: aspect scores = tanh in [-1,1]; sentiment scores are
// O(1) -> plain exp() is safe and equals the reference's shifted softmax.
// Query-side additive terms are constant over t and cancel in the softmax.
// ---------------------------------------------------------------------------
__global__ void __launch_bounds__(NTHREADS, 8) k_main(
    const float* __restrict__ aspect,            // [B,D]
    const float* __restrict__ sentiment_memory,  // [B,T,D]
    const float* __restrict__ aspect_memory,     // [B,T,D]
    const float* __restrict__ mask,              // [B,T]
    const float* __restrict__ W_mul,             // [D,D]
    const float* __restrict__ b_mul,             // [1]
    const float* __restrict__ w_ss,              // [2D] (only [:D] matters)
    const float* __restrict__ w_sa,              // [2D]
    float* __restrict__ out)                     // [2*B*D]
{
    __shared__ __align__(16) float s_red[2 * NW * D_];   // 8 KB (P half, Q half)
    __shared__ float s_lred[2 * NW];
    __shared__ int s_doc;

    const int cta   = blockIdx.x;
    const int ctype = cta & 1;          // 0 = aspect, 1 = sentiment
    const int tcta  = cta >> 1;
    const int tid   = threadIdx.x;
    const int w     = tid >> 5, lane = tid & 31;

    const int nit = (NIT - tcta + CPT - 1) / CPT;   // 6 or 7 chunks

    if (ctype == 0) {
        // ---- mids GEMV by aspect CTAs only (sentiment half streams now) ----
        const int gid = tcta * NW + w;
        for (int idx = gid; idx < NDOTS; idx += CPT * NW) {
            const int b   = idx >> 8;
            const int row = idx & (D_ - 1);
            const float4* Wr = (const float4*)(W_mul + (size_t)row * D_);
            const float4* Ar = (const float4*)(aspect + (size_t)b * D_);
            float p = dot8(Wr[lane], Ar[lane], Wr[32 + lane], Ar[32 + lane]);
            p = warp_sum(p);
            if (lane == 0) g_mids[b * D_ + row] = p;
        }
        __threadfence();   // release own g_mids writes (every thread)
        __syncthreads();
        // Replay-safe barrier among the CPT aspect CTAs (monotonic counter).
        if (tid == 0) {
            const unsigned old = atomicAdd(&g_bar, 1u);
            const unsigned tgt = (old / CPT + 1u) * CPT;
            while (*(volatile unsigned*)&g_bar < tgt) { }
        }
        __syncthreads();
        __threadfence();   // acquire
    }

    if (ctype == 1) {
        // ------------- sentiment: two softmax streams -------------
        const float4 w10 = *(const float4*)(w_ss + lane * 4);
        const float4 w11 = *(const float4*)(w_ss + 128 + lane * 4);
        const float4 w20 = *(const float4*)(w_sa + lane * 4);
        const float4 w21 = *(const float4*)(w_sa + 128 + lane * 4);

        for (int j = 0; j < nit; j++) {
            const int e = tcta + CPT * j;
            const int b = e >> 5, s = e & 31;
            const float4* m4  = (const float4*)(sentiment_memory
                              + ((size_t)b * T_ + (size_t)s * ROWS_ITEM
                                 + w * ROWS_W) * D_);
            const float* mrow = mask + (size_t)b * T_ + (size_t)s * ROWS_ITEM
                              + w * ROWS_W;

            float l1 = 0.f, l2 = 0.f;
            float4 P0 = {0,0,0,0}, P1 = {0,0,0,0};
            float4 Q0 = {0,0,0,0}, Q1 = {0,0,0,0};

#pragma unroll
            for (int rr = 0; rr < ROWS_W; rr += 2) {
                const float4 r0a = __ldcs(&m4[(size_t)rr * 64 + lane]);
                const float4 r1a = __ldcs(&m4[(size_t)rr * 64 + 32 + lane]);
                const float4 r0b = __ldcs(&m4[(size_t)(rr + 1) * 64 + lane]);
                const float4 r1b = __ldcs(&m4[(size_t)(rr + 1) * 64 + 32 + lane]);
                const float mka = mrow[rr];
                const float mkb = mrow[rr + 1];

                float d1a = dot8(r0a, w10, r1a, w11);
                float d2a = dot8(r0a, w20, r1a, w21);
                float d1b = dot8(r0b, w10, r1b, w11);
                float d2b = dot8(r0b, w20, r1b, w21);
#pragma unroll
                for (int o = 16; o > 0; o >>= 1) {
                    d1a += __shfl_xor_sync(0xffffffffu, d1a, o);
                    d2a += __shfl_xor_sync(0xffffffffu, d2a, o);
                    d1b += __shfl_xor_sync(0xffffffffu, d1b, o);
                    d2b += __shfl_xor_sync(0xffffffffu, d2b, o);
                }
                const float pe1a = __expf(d1a) * mka;
                const float pe2a = __expf(d2a) * mka;
                const float pe1b = __expf(d1b) * mkb;
                const float pe2b = __expf(d2b) * mkb;
                l1 += pe1a + pe1b;
                l2 += pe2a + pe2b;
                FMA4(P0, pe1a, r0a)  FMA4(P1, pe1a, r1a)
                FMA4(Q0, pe2a, r0a)  FMA4(Q1, pe2a, r1a)
                FMA4(P0, pe1b, r0b)  FMA4(P1, pe1b, r1b)
                FMA4(Q0, pe2b, r0b)  FMA4(Q1, pe2b, r1b)
            }

            // ---- fused flush: both streams, one barrier pair ----
            *(float4*)&s_red[w * D_ + lane * 4]                 = P0;
            *(float4*)&s_red[w * D_ + 128 + lane * 4]           = P1;
            *(float4*)&s_red[NW * D_ + w * D_ + lane * 4]       = Q0;
            *(float4*)&s_red[NW * D_ + w * D_ + 128 + lane * 4] = Q1;
            if (lane == 0) { s_lred[w] = l1; s_lred[NW + w] = l2; }
            __syncthreads();
            {
                float v1a = 0.f, v1b = 0.f, v2a = 0.f, v2b = 0.f;
#pragma unroll
                for (int ww = 0; ww < NW; ww++) {
                    v1a += s_red[ww * D_ + tid];
                    v1b += s_red[ww * D_ + tid + 128];
                    v2a += s_red[NW * D_ + ww * D_ + tid];
                    v2b += s_red[NW * D_ + ww * D_ + tid + 128];
                }
                const float L1 = s_lred[0] + s_lred[1] + s_lred[2] + s_lred[3];
                const float L2 = s_lred[4] + s_lred[5] + s_lred[6] + s_lred[7];
                g_p1[e][tid] = v1a;  g_p1[e][tid + 128] = v1b;
                g_p2[e][tid] = v2a;  g_p2[e][tid + 128] = v2b;
                if (tid == 0) { g_p1[e][256] = L1; g_p2[e][256] = L2; }
            }
            __threadfence();   // release own partial STGs (every thread)
            __syncthreads();
            if (tid == 0) {
                const unsigned old = atomicAdd(&g_cnt_s[b], 1u);
                s_doc = ((old & 31u) == 31u);
            }
            __syncthreads();
            if (s_doc) {
                __threadfence();   // acquire (per thread)
                float V1a = 0.f, V1b = 0.f, V2a = 0.f, V2b = 0.f;
                float L1 = 0.f, L2 = 0.f;
#pragma unroll 8
                for (int s2 = 0; s2 < S_; s2++) {
                    const int i = b * S_ + s2;
                    V1a += __ldcg(&g_p1[i][tid]);
                    V1b += __ldcg(&g_p1[i][tid + 128]);
                    V2a += __ldcg(&g_p2[i][tid]);
                    V2b += __ldcg(&g_p2[i][tid + 128]);
                    L1  += __ldcg(&g_p1[i][256]);
                    L2  += __ldcg(&g_p2[i][256]);
                }
                out[b * D_ + tid]       = 0.5f * (V1a / L1) + 0.5f * (V2a / L2);
                out[b * D_ + tid + 128] = 0.5f * (V1b / L1) + 0.5f * (V2b / L2);
            }
            __syncthreads();
        }
    } else {
        // ------------- aspect: fast-tanh-score softmax -------------
        const float bm = b_mul[0];
        for (int j = 0; j < nit; j++) {
            const int e = tcta + CPT * j;
            const int b = e >> 5, s = e & 31;
            const float4* m4 = (const float4*)(aspect_memory
                             + ((size_t)b * T_ + (size_t)s * ROWS_ITEM
                                + w * ROWS_W) * D_);
            const float4 md0 = *(const float4*)(g_mids + b * D_ + lane * 4);
            const float4 md1 = *(const float4*)(g_mids + b * D_ + 128 + lane * 4);

            float l = 0.f;
            float4 A0 = {0,0,0,0}, A1 = {0,0,0,0};

#pragma unroll
            for (int rr = 0; rr < ROWS_W; rr += 2) {
                const float4 r0a = __ldcs(&m4[(size_t)rr * 64 + lane]);
                const float4 r1a = __ldcs(&m4[(size_t)rr * 64 + 32 + lane]);
                const float4 r0b = __ldcs(&m4[(size_t)(rr + 1) * 64 + lane]);
                const float4 r1b = __ldcs(&m4[(size_t)(rr + 1) * 64 + 32 + lane]);

                float pa = dot8(r0a, md0, r1a, md1);
                float pb = dot8(r0b, md0, r1b, md1);
#pragma unroll
                for (int o = 16; o > 0; o >>= 1) {
                    pa += __shfl_xor_sync(0xffffffffu, pa, o);
                    pb += __shfl_xor_sync(0xffffffffu, pb, o);
                }
                const float pea = __expf(fast_tanh(pa + bm));
                const float peb = __expf(fast_tanh(pb + bm));
                l += pea + peb;
                FMA4(A0, pea, r0a)  FMA4(A1, pea, r1a)
                FMA4(A0, peb, r0b)  FMA4(A1, peb, r1b)
            }

            // ---- flush (single stream) ----
            *(float4*)&s_red[w * D_ + lane * 4]       = A0;
            *(float4*)&s_red[w * D_ + 128 + lane * 4] = A1;
            if (lane == 0) s_lred[w] = l;
            __syncthreads();
            {
                float va = 0.f, vb = 0.f;
#pragma unroll
                for (int ww = 0; ww < NW; ww++) {
                    va += s_red[ww * D_ + tid];
                    vb += s_red[ww * D_ + tid + 128];
                }
                const float L = s_lred[0] + s_lred[1] + s_lred[2] + s_lred[3];
                g_pa[e][tid] = va;  g_pa[e][tid + 128] = vb;
                if (tid == 0) g_pa[e][256] = L;
            }
            __threadfence();   // release (every thread)
            __syncthreads();
            if (tid == 0) {
                const unsigned old = atomicAdd(&g_cnt_a[b], 1u);
                s_doc = ((old & 31u) == 31u);
            }
            __syncthreads();
            if (s_doc) {
                __threadfence();   // acquire (per thread)
                float Va = 0.f, Vb = 0.f, La = 0.f;
#pragma unroll 8
                for (int s2 = 0; s2 < S_; s2++) {
                    const int i = b * S_ + s2;
                    Va += __ldcg(&g_pa[i][tid]);
                    Vb += __ldcg(&g_pa[i][tid + 128]);
                    La += __ldcg(&g_pa[i][256]);
                }
                out[B_ * D_ + b * D_ + tid] = aspect[b * D_ + tid] + Va / La;
                out[B_ * D_ + b * D_ + tid + 128] =
                    aspect[b * D_ + tid + 128] + Vb / La;
            }
            __syncthreads();
        }
    }
}

// ---------------------------------------------------------------------------
// kernel_launch. Inputs (metadata order):
//  0 sentiment  1 aspect  2 sentiment_memory  3 aspect_memory  4 mask
//  5 W_mul  6 b_mul  7 w_ss  8 b_ss  9 w_sa  10 b_sa
// Query-side additive terms (w[D:], biases) cancel in the softmax -> unused.
// Output: sentiment_out [0, B*D), aspect_out [B*D, 2*B*D).
// ---------------------------------------------------------------------------
extern "C" void kernel_launch(void* const* d_in, const int* in_sizes, int n_in,
                              void* d_out, int out_size)
{
    const float* aspect           = (const float*)d_in[1];
    const float* sentiment_memory = (const float*)d_in[2];
    const float* aspect_memory    = (const float*)d_in[3];
    const float* mask             = (const float*)d_in[4];
    const float* W_mul            = (const float*)d_in[5];
    const float* b_mul            = (const float*)d_in[6];
    const float* w_ss             = (const float*)d_in[7];
    const float* w_sa             = (const float*)d_in[9];
    float* out = (float*)d_out;

    k_main<<<GRID_MAIN, NTHREADS>>>(
        aspect, sentiment_memory, aspect_memory, mask, W_mul, b_mul,
        w_ss, w_sa, out);
}

// round 16
// speedup vs baseline: 1.3995x; 1.0351x over previous
#include <cuda_runtime.h>
#include <cstdint>

// Problem constants: B=128, T=2048, D=256, LAMDA=0.5
#define B_ 128
#define T_ 2048
#define D_ 256
#define S_ 32                          // 64-row chunks per (b, tensor)
#define ROWS_ITEM 64
#define NW 4                           // warps per CTA (small CTA -> cheap flush)
#define NTHREADS 128
#define OCC 6                          // CTAs/SM (regs ~80 for double-buffer)
#define GRID_MAIN (148 * OCC)          // 888 — single wave at occupancy 6
#define CPT (GRID_MAIN / 2)            // 444 CTAs per tensor type
#define NIT (B_ * S_)                  // 4096 chunks per tensor
#define NDOTS (B_ * D_)                // 32768 mids row-dots
#define ROWS_W (ROWS_ITEM / NW)        // 16 rows per warp per chunk

// Globals (zero-initialized). Counters monotonic+modular -> graph-replay safe.
// Partials are written fresh every launch before being read (proven scheme).
__device__ float g_mids[B_ * D_];
__device__ float g_pa[NIT][258];   // aspect partials (acc[256], L at [256])
__device__ float g_p1[NIT][258];   // sentiment-sentiment partials
__device__ float g_p2[NIT][258];   // sentiment-aspect partials
__device__ unsigned g_bar;         // aspect-side barrier counter (+CPT/launch)
__device__ unsigned g_cnt_s[B_];   // sentiment chunk counters (+32/launch)
__device__ unsigned g_cnt_a[B_];   // aspect chunk counters    (+32/launch)

__device__ __forceinline__ float warp_sum(float v) {
#pragma unroll
    for (int o = 16; o > 0; o >>= 1) v += __shfl_xor_sync(0xffffffffu, v, o);
    return v;
}
__device__ __forceinline__ float dot8(float4 a, float4 b, float4 c, float4 d) {
    return a.x*b.x + a.y*b.y + a.z*b.z + a.w*b.w
         + c.x*d.x + c.y*d.y + c.z*d.z + c.w*d.w;
}
// Fast tanh (inf-safe |x| form; exact +-1 saturation at large |x|).
__device__ __forceinline__ float fast_tanh(float x) {
    const float t = __expf(2.0f * fabsf(x));
    const float r = 1.0f - __fdividef(2.0f, t + 1.0f);
    return copysignf(r, x);
}
#define FMA4(acc, s, r) \
    acc.x += (s)*(r).x; acc.y += (s)*(r).y; acc.z += (s)*(r).z; acc.w += (s)*(r).w;

// ---------------------------------------------------------------------------
// k_main: ONE kernel, grid = 888 (6 CTAs/SM, single wave). Inner loops are
// SOFTWARE-PIPELINED: pair k+1's 4 LDG.128s are issued BEFORE pair k's
// shfl-reduction chain, so each warp always has ~2KB of loads in flight
// during the ~230-cycle compute phase (the 50% load-duty gap was the
// measured DRAM ceiling in R10-R15). Full unroll makes the double-buffer
// rotation pure register renaming (~80 regs -> occupancy 6).
// Proven cross-CTA protocol: per-chunk partial arrays (plain STGs) +
// per-chunk counter; the CTA seeing (old&31)==31 for b does b's combine.
// Even CTAs: mids GEMV -> barrier (aspect half only) -> stream aspect_memory.
// Odd CTAs:  stream sentiment_memory immediately (two softmax streams).
// No online max needed: aspect scores = tanh in [-1,1]; sentiment scores are
// O(1) -> plain exp() is safe and equals the reference's shifted softmax.
// Query-side additive terms are constant over t and cancel in the softmax.
// ---------------------------------------------------------------------------
__global__ void __launch_bounds__(NTHREADS, OCC) k_main(
    const float* __restrict__ aspect,            // [B,D]
    const float* __restrict__ sentiment_memory,  // [B,T,D]
    const float* __restrict__ aspect_memory,     // [B,T,D]
    const float* __restrict__ mask,              // [B,T]
    const float* __restrict__ W_mul,             // [D,D]
    const float* __restrict__ b_mul,             // [1]
    const float* __restrict__ w_ss,              // [2D] (only [:D] matters)
    const float* __restrict__ w_sa,              // [2D]
    float* __restrict__ out)                     // [2*B*D]
{
    __shared__ __align__(16) float s_red[2 * NW * D_];   // 8 KB (P half, Q half)
    __shared__ float s_lred[2 * NW];
    __shared__ int s_doc;

    const int cta   = blockIdx.x;
    const int ctype = cta & 1;          // 0 = aspect, 1 = sentiment
    const int tcta  = cta >> 1;
    const int tid   = threadIdx.x;
    const int w     = tid >> 5, lane = tid & 31;

    const int nit = (NIT - tcta + CPT - 1) / CPT;   // 9 or 10 chunks

    if (ctype == 0) {
        // ---- mids GEMV by aspect CTAs only (sentiment half streams now) ----
        const int gid = tcta * NW + w;
        for (int idx = gid; idx < NDOTS; idx += CPT * NW) {
            const int b   = idx >> 8;
            const int row = idx & (D_ - 1);
            const float4* Wr = (const float4*)(W_mul + (size_t)row * D_);
            const float4* Ar = (const float4*)(aspect + (size_t)b * D_);
            float p = dot8(Wr[lane], Ar[lane], Wr[32 + lane], Ar[32 + lane]);
            p = warp_sum(p);
            if (lane == 0) g_mids[b * D_ + row] = p;
        }
        __threadfence();   // release own g_mids writes (every thread)
        __syncthreads();
        // Replay-safe barrier among the CPT aspect CTAs (monotonic counter).
        if (tid == 0) {
            const unsigned old = atomicAdd(&g_bar, 1u);
            const unsigned tgt = (old / CPT + 1u) * CPT;
            while (*(volatile unsigned*)&g_bar < tgt) { }
        }
        __syncthreads();
        __threadfence();   // acquire
    }

    if (ctype == 1) {
        // ------------- sentiment: two softmax streams -------------
        const float4 w10 = *(const float4*)(w_ss + lane * 4);
        const float4 w11 = *(const float4*)(w_ss + 128 + lane * 4);
        const float4 w20 = *(const float4*)(w_sa + lane * 4);
        const float4 w21 = *(const float4*)(w_sa + 128 + lane * 4);

        for (int j = 0; j < nit; j++) {
            const int e = tcta + CPT * j;
            const int b = e >> 5, s = e & 31;
            const float4* m4  = (const float4*)(sentiment_memory
                              + ((size_t)b * T_ + (size_t)s * ROWS_ITEM
                                 + w * ROWS_W) * D_);
            const float* mrow = mask + (size_t)b * T_ + (size_t)s * ROWS_ITEM
                              + w * ROWS_W;

            float l1 = 0.f, l2 = 0.f;
            float4 P0 = {0,0,0,0}, P1 = {0,0,0,0};
            float4 Q0 = {0,0,0,0}, Q1 = {0,0,0,0};

            // Software pipeline: preload pair 0, then in each step issue
            // pair p+1's loads BEFORE processing pair p.
            float4 Ca0 = __ldcs(&m4[lane]);
            float4 Ca1 = __ldcs(&m4[32 + lane]);
            float4 Cb0 = __ldcs(&m4[64 + lane]);
            float4 Cb1 = __ldcs(&m4[96 + lane]);
            float mka = mrow[0], mkb = mrow[1];

#pragma unroll
            for (int p = 0; p < ROWS_W / 2; p++) {
                float4 Na0, Na1, Nb0, Nb1;
                float nka = 0.f, nkb = 0.f;
                if (p < ROWS_W / 2 - 1) {
                    const int r2 = 2 * p + 2;
                    Na0 = __ldcs(&m4[(size_t)r2 * 64 + lane]);
                    Na1 = __ldcs(&m4[(size_t)r2 * 64 + 32 + lane]);
                    Nb0 = __ldcs(&m4[(size_t)(r2 + 1) * 64 + lane]);
                    Nb1 = __ldcs(&m4[(size_t)(r2 + 1) * 64 + 32 + lane]);
                    nka = mrow[r2];
                    nkb = mrow[r2 + 1];
                }

                float d1a = dot8(Ca0, w10, Ca1, w11);
                float d2a = dot8(Ca0, w20, Ca1, w21);
                float d1b = dot8(Cb0, w10, Cb1, w11);
                float d2b = dot8(Cb0, w20, Cb1, w21);
#pragma unroll
                for (int o = 16; o > 0; o >>= 1) {
                    d1a += __shfl_xor_sync(0xffffffffu, d1a, o);
                    d2a += __shfl_xor_sync(0xffffffffu, d2a, o);
                    d1b += __shfl_xor_sync(0xffffffffu, d1b, o);
                    d2b += __shfl_xor_sync(0xffffffffu, d2b, o);
                }
                const float pe1a = __expf(d1a) * mka;
                const float pe2a = __expf(d2a) * mka;
                const float pe1b = __expf(d1b) * mkb;
                const float pe2b = __expf(d2b) * mkb;
                l1 += pe1a + pe1b;
                l2 += pe2a + pe2b;
                FMA4(P0, pe1a, Ca0)  FMA4(P1, pe1a, Ca1)
                FMA4(Q0, pe2a, Ca0)  FMA4(Q1, pe2a, Ca1)
                FMA4(P0, pe1b, Cb0)  FMA4(P1, pe1b, Cb1)
                FMA4(Q0, pe2b, Cb0)  FMA4(Q1, pe2b, Cb1)

                if (p < ROWS_W / 2 - 1) {
                    Ca0 = Na0; Ca1 = Na1; Cb0 = Nb0; Cb1 = Nb1;
                    mka = nka; mkb = nkb;
                }
            }

            // ---- fused flush: both streams, one barrier pair ----
            *(float4*)&s_red[w * D_ + lane * 4]                 = P0;
            *(float4*)&s_red[w * D_ + 128 + lane * 4]           = P1;
            *(float4*)&s_red[NW * D_ + w * D_ + lane * 4]       = Q0;
            *(float4*)&s_red[NW * D_ + w * D_ + 128 + lane * 4] = Q1;
            if (lane == 0) { s_lred[w] = l1; s_lred[NW + w] = l2; }
            __syncthreads();
            {
                float v1a = 0.f, v1b = 0.f, v2a = 0.f, v2b = 0.f;
#pragma unroll
                for (int ww = 0; ww < NW; ww++) {
                    v1a += s_red[ww * D_ + tid];
                    v1b += s_red[ww * D_ + tid + 128];
                    v2a += s_red[NW * D_ + ww * D_ + tid];
                    v2b += s_red[NW * D_ + ww * D_ + tid + 128];
                }
                const float L1 = s_lred[0] + s_lred[1] + s_lred[2] + s_lred[3];
                const float L2 = s_lred[4] + s_lred[5] + s_lred[6] + s_lred[7];
                g_p1[e][tid] = v1a;  g_p1[e][tid + 128] = v1b;
                g_p2[e][tid] = v2a;  g_p2[e][tid + 128] = v2b;
                if (tid == 0) { g_p1[e][256] = L1; g_p2[e][256] = L2; }
            }
            __threadfence();   // release own partial STGs (every thread)
            __syncthreads();
            if (tid == 0) {
                const unsigned old = atomicAdd(&g_cnt_s[b], 1u);
                s_doc = ((old & 31u) == 31u);
            }
            __syncthreads();
            if (s_doc) {
                __threadfence();   // acquire (per thread)
                float V1a = 0.f, V1b = 0.f, V2a = 0.f, V2b = 0.f;
                float L1 = 0.f, L2 = 0.f;
#pragma unroll 8
                for (int s2 = 0; s2 < S_; s2++) {
                    const int i = b * S_ + s2;
                    V1a += __ldcg(&g_p1[i][tid]);
                    V1b += __ldcg(&g_p1[i][tid + 128]);
                    V2a += __ldcg(&g_p2[i][tid]);
                    V2b += __ldcg(&g_p2[i][tid + 128]);
                    L1  += __ldcg(&g_p1[i][256]);
                    L2  += __ldcg(&g_p2[i][256]);
                }
                out[b * D_ + tid]       = 0.5f * (V1a / L1) + 0.5f * (V2a / L2);
                out[b * D_ + tid + 128] = 0.5f * (V1b / L1) + 0.5f * (V2b / L2);
            }
            __syncthreads();
        }
    } else {
        // ------------- aspect: fast-tanh-score softmax -------------
        const float bm = b_mul[0];
        for (int j = 0; j < nit; j++) {
            const int e = tcta + CPT * j;
            const int b = e >> 5, s = e & 31;
            const float4* m4 = (const float4*)(aspect_memory
                             + ((size_t)b * T_ + (size_t)s * ROWS_ITEM
                                + w * ROWS_W) * D_);
            const float4 md0 = *(const float4*)(g_mids + b * D_ + lane * 4);
            const float4 md1 = *(const float4*)(g_mids + b * D_ + 128 + lane * 4);

            float l = 0.f;
            float4 A0 = {0,0,0,0}, A1 = {0,0,0,0};

            float4 Ca0 = __ldcs(&m4[lane]);
            float4 Ca1 = __ldcs(&m4[32 + lane]);
            float4 Cb0 = __ldcs(&m4[64 + lane]);
            float4 Cb1 = __ldcs(&m4[96 + lane]);

#pragma unroll
            for (int p = 0; p < ROWS_W / 2; p++) {
                float4 Na0, Na1, Nb0, Nb1;
                if (p < ROWS_W / 2 - 1) {
                    const int r2 = 2 * p + 2;
                    Na0 = __ldcs(&m4[(size_t)r2 * 64 + lane]);
                    Na1 = __ldcs(&m4[(size_t)r2 * 64 + 32 + lane]);
                    Nb0 = __ldcs(&m4[(size_t)(r2 + 1) * 64 + lane]);
                    Nb1 = __ldcs(&m4[(size_t)(r2 + 1) * 64 + 32 + lane]);
                }

                float pa = dot8(Ca0, md0, Ca1, md1);
                float pb = dot8(Cb0, md0, Cb1, md1);
#pragma unroll
                for (int o = 16; o > 0; o >>= 1) {
                    pa += __shfl_xor_sync(0xffffffffu, pa, o);
                    pb += __shfl_xor_sync(0xffffffffu, pb, o);
                }
                const float pea = __expf(fast_tanh(pa + bm));
                const float peb = __expf(fast_tanh(pb + bm));
                l += pea + peb;
                FMA4(A0, pea, Ca0)  FMA4(A1, pea, Ca1)
                FMA4(A0, peb, Cb0)  FMA4(A1, peb, Cb1)

                if (p < ROWS_W / 2 - 1) {
                    Ca0 = Na0; Ca1 = Na1; Cb0 = Nb0; Cb1 = Nb1;
                }
            }

            // ---- flush (single stream) ----
            *(float4*)&s_red[w * D_ + lane * 4]       = A0;
            *(float4*)&s_red[w * D_ + 128 + lane * 4] = A1;
            if (lane == 0) s_lred[w] = l;
            __syncthreads();
            {
                float va = 0.f, vb = 0.f;
#pragma unroll
                for (int ww = 0; ww < NW; ww++) {
                    va += s_red[ww * D_ + tid];
                    vb += s_red[ww * D_ + tid + 128];
                }
                const float L = s_lred[0] + s_lred[1] + s_lred[2] + s_lred[3];
                g_pa[e][tid] = va;  g_pa[e][tid + 128] = vb;
                if (tid == 0) g_pa[e][256] = L;
            }
            __threadfence();   // release (every thread)
            __syncthreads();
            if (tid == 0) {
                const unsigned old = atomicAdd(&g_cnt_a[b], 1u);
                s_doc = ((old & 31u) == 31u);
            }
            __syncthreads();
            if (s_doc) {
                __threadfence();   // acquire (per thread)
                float Va = 0.f, Vb = 0.f, La = 0.f;
#pragma unroll 8
                for (int s2 = 0; s2 < S_; s2++) {
                    const int i = b * S_ + s2;
                    Va += __ldcg(&g_pa[i][tid]);
                    Vb += __ldcg(&g_pa[i][tid + 128]);
                    La += __ldcg(&g_pa[i][256]);
                }
                out[B_ * D_ + b * D_ + tid] = aspect[b * D_ + tid] + Va / La;
                out[B_ * D_ + b * D_ + tid + 128] =
                    aspect[b * D_ + tid + 128] + Vb / La;
            }
            __syncthreads();
        }
    }
}

// ---------------------------------------------------------------------------
// kernel_launch. Inputs (metadata order):
//  0 sentiment  1 aspect  2 sentiment_memory  3 aspect_memory  4 mask
//  5 W_mul  6 b_mul  7 w_ss  8 b_ss  9 w_sa  10 b_sa
// Query-side additive terms (w[D:], biases) cancel in the softmax -> unused.
// Output: sentiment_out [0, B*D), aspect_out [B*D, 2*B*D).
// ---------------------------------------------------------------------------
extern "C" void kernel_launch(void* const* d_in, const int* in_sizes, int n_in,
                              void* d_out, int out_size)
{
    const float* aspect           = (const float*)d_in[1];
    const float* sentiment_memory = (const float*)d_in[2];
    const float* aspect_memory    = (const float*)d_in[3];
    const float* mask             = (const float*)d_in[4];
    const float* W_mul            = (const float*)d_in[5];
    const float* b_mul            = (const float*)d_in[6];
    const float* w_ss             = (const float*)d_in[7];
    const float* w_sa             = (const float*)d_in[9];
    float* out = (float*)d_out;

    k_main<<<GRID_MAIN, NTHREADS>>>(
        aspect, sentiment_memory, aspect_memory, mask, W_mul, b_mul,
        w_ss, w_sa, out);
}